// round 15
// baseline (speedup 1.0000x reference)
#include <cuda_runtime.h>
#include <cuda_fp16.h>
#include <cstdint>

// GroupQuerySelfAttention: B=2, S=2048, D=768, NH=12, GH=4 (rep=3), HD=64
// MASK_FILL = -1e-9 => masked p == exp(-1e-9) == 1.0f exactly; V suffix sums
// let us skip ~half the attention tiles. R15: GEMM warp tile widened to
// 32m x 64n (A-frag reuse halves LDS/mma), CTA 256m x 64n; converts merged.
// All fp16 mma + cp.async. Buggy merge == attention out stored [B,NH,HD,S].

namespace {
constexpr int kB  = 2;
constexpr int kS  = 2048;
constexpr int kD  = 768;
constexpr int kNH = 12;
constexpr int kGH = 4;
constexpr int kHD = 64;
constexpr int kREP = 3;
constexpr float kScale = 0.125f;
}

__device__ __half g_Xh [(size_t)kB * kS * kD];
__device__ __half g_WqT[(size_t)kD * kD];
__device__ __half g_WkT[(size_t)(kGH * kHD) * kD];
__device__ __half g_WvT[(size_t)(kGH * kHD) * kD];
__device__ __half g_WoT[(size_t)kD * kD];
__device__ __half g_Qh [(size_t)kB * kNH * kS * kHD];
__device__ __half g_Kh [(size_t)kB * kGH * kS * kHD];
__device__ __half g_Vh [(size_t)kB * kGH * kHD * kS];  // [b, g, hd, s]
__device__ __half g_Oh [(size_t)kB * kNH * kHD * kS];  // [b, h, hd, q]
__device__ float  g_Vsuf[(size_t)kB * kGH * 33 * kHD];

// ---------------------------------------------------------------------------
__device__ __forceinline__ void mma_f16(float* d, const uint32_t* a,
                                        uint32_t b0, uint32_t b1) {
    asm volatile(
        "mma.sync.aligned.m16n8k16.row.col.f32.f16.f16.f32 "
        "{%0,%1,%2,%3}, {%4,%5,%6,%7}, {%8,%9}, {%0,%1,%2,%3};"
        : "+f"(d[0]), "+f"(d[1]), "+f"(d[2]), "+f"(d[3])
        : "r"(a[0]), "r"(a[1]), "r"(a[2]), "r"(a[3]), "r"(b0), "r"(b1));
}
__device__ __forceinline__ uint32_t pack_f16(float lo, float hi) {
    uint32_t r;
    asm("cvt.rn.f16x2.f32 %0, %1, %2;" : "=r"(r) : "f"(hi), "f"(lo));
    return r;
}
__device__ __forceinline__ uint32_t smem_u32(const void* p) {
    uint32_t a;
    asm("{ .reg .u64 t; cvta.to.shared.u64 t, %1; cvt.u32.u64 %0, t; }"
        : "=r"(a) : "l"(p));
    return a;
}
__device__ __forceinline__ void cp16(uint32_t dst, const void* src) {
    asm volatile("cp.async.cg.shared.global [%0], [%1], 16;"
                 :: "r"(dst), "l"(src) : "memory");
}
__device__ __forceinline__ void cp_commit() {
    asm volatile("cp.async.commit_group;" ::: "memory");
}
__device__ __forceinline__ void cp_wait1() {
    asm volatile("cp.async.wait_group 1;" ::: "memory");
}
__device__ __forceinline__ uint32_t ld32s(const __half* p) {
    return *reinterpret_cast<const uint32_t*>(p);
}

// ---------------------------------------------------------------------------
// Merged prep: blocks [0,3072) convert x; [3072,4608) transpose+convert W.
// ---------------------------------------------------------------------------
__global__ __launch_bounds__(256) void convert_all(
    const float* __restrict__ x,
    const float* __restrict__ Wq, const float* __restrict__ Wk,
    const float* __restrict__ Wv, const float* __restrict__ Wo)
{
    if (blockIdx.x < 3072) {
        const int idx = blockIdx.x * 256 + threadIdx.x;
        float4 v = reinterpret_cast<const float4*>(x)[idx];
        uint2 p;
        p.x = pack_f16(v.x, v.y);
        p.y = pack_f16(v.z, v.w);
        reinterpret_cast<uint2*>(g_Xh)[idx] = p;
        return;
    }
    __shared__ float t[32][33];
    const int wb = blockIdx.x - 3072;           // 0..1535
    const int c0 = (wb & 63) * 32;              // concat col [0,2048)
    const int k0 = (wb >> 6) * 32;              // k [0,768)
    const float* W; __half* dst; int Nw, cl;
    if (c0 < 768)       { W = Wq; dst = g_WqT; Nw = 768; cl = c0; }
    else if (c0 < 1024) { W = Wk; dst = g_WkT; Nw = 256; cl = c0 - 768; }
    else if (c0 < 1280) { W = Wv; dst = g_WvT; Nw = 256; cl = c0 - 1024; }
    else                { W = Wo; dst = g_WoT; Nw = 768; cl = c0 - 1280; }
    const int tx = threadIdx.x & 31, ty = threadIdx.x >> 5;
    #pragma unroll
    for (int j = 0; j < 4; ++j)
        t[ty + j * 8][tx] = W[(size_t)(k0 + ty + j * 8) * Nw + cl + tx];
    __syncthreads();
    #pragma unroll
    for (int j = 0; j < 4; ++j) {
        const int n = ty + j * 8;
        dst[(size_t)(cl + n) * kD + k0 + tx] = __float2half_rn(t[tx][n]);
    }
}

// V suffix tile-colsum (proven R14): warp per (bg,hd), uint4 loads, shfl scan.
__global__ __launch_bounds__(256) void vsuf_kernel()
{
    const int warp = threadIdx.x >> 5, lane = threadIdx.x & 31;
    const int bg = blockIdx.x >> 3;
    const int hd = (blockIdx.x & 7) * 8 + warp;
    const __half* row = g_Vh + ((size_t)bg * kHD + hd) * kS + lane * 64;

    float s = 0.f;
    #pragma unroll
    for (int i = 0; i < 8; ++i) {
        const uint4 v = *reinterpret_cast<const uint4*>(row + i * 8);
        const __half2* h2 = reinterpret_cast<const __half2*>(&v);
        #pragma unroll
        for (int j = 0; j < 4; ++j) {
            const float2 f = __half22float2(h2[j]);
            s += f.x + f.y;
        }
    }
    #pragma unroll
    for (int off = 1; off < 32; off <<= 1) {
        const float up = __shfl_down_sync(0xffffffffu, s, off);
        if (lane + off < 32) s += up;
    }
    float* dst = g_Vsuf + (size_t)bg * 33 * kHD + hd;
    dst[(size_t)lane * kHD] = s;
    if (lane == 0) dst[(size_t)32 * kHD] = 0.f;
}

// ---------------------------------------------------------------------------
// f16 GEMM core, CTA 256m x 64n, warp 32m x 64n (A reuse: 1.5 LDS/mma).
// 3-stage cp.async; stage = A[256][40] + W[64][40] f16 = 25600 B.
// ---------------------------------------------------------------------------
namespace {
constexpr int GST = 40;
constexpr int GA_B = 256 * GST * 2;            // 20480
constexpr int GW_B = 64 * GST * 2;             // 5120
constexpr int GSTAGE_B = GA_B + GW_B;          // 25600
constexpr int SMEM_GEMM = 3 * GSTAGE_B;        // 76800
constexpr int TPAD = 264;                      // V-transpose staging stride
}

__device__ __forceinline__ void gemm16_mainloop(
    uint32_t sb, const char* smem,
    const __half* __restrict__ Arow, const __half* __restrict__ Wrow,
    int w, int lr, int lc, int tid, float (&acc)[2][8][4])
{
    auto stage = [&](int ch, int s) {
        const int k0 = ch * 32;
        const uint32_t ab = sb + s * GSTAGE_B;
        const uint32_t wb = ab + GA_B;
        #pragma unroll
        for (int j = 0; j < 4; ++j) {
            const int idx = tid + 256 * j;          // 1024: 256 rows x 4 chunks
            const int r = idx >> 2, c4 = idx & 3;
            cp16(ab + (uint32_t)(r * GST + c4 * 8) * 2,
                 Arow + (size_t)r * kD + k0 + c4 * 8);
        }
        {
            const int r = tid >> 2, c4 = tid & 3;
            cp16(wb + (uint32_t)(r * GST + c4 * 8) * 2,
                 Wrow + (size_t)r * kD + k0 + c4 * 8);
        }
        cp_commit();
    };

    stage(0, 0);
    stage(1, 1);

    const int nch = kD / 32;
    int buf = 0;
    for (int ch = 0; ch < nch; ++ch) {
        cp_wait1();
        __syncthreads();
        const __half* Ab = reinterpret_cast<const __half*>(smem + buf * GSTAGE_B);
        const __half* Wb = Ab + 256 * GST;
        #pragma unroll
        for (int ks = 0; ks < 2; ++ks) {
            const int cb = ks * 16 + 2 * lc;
            uint32_t a[2][4];
            #pragma unroll
            for (int hh = 0; hh < 2; ++hh) {
                const int r0 = w * 32 + hh * 16 + lr;
                a[hh][0] = ld32s(Ab + r0 * GST + cb);
                a[hh][1] = ld32s(Ab + (r0 + 8) * GST + cb);
                a[hh][2] = ld32s(Ab + r0 * GST + cb + 8);
                a[hh][3] = ld32s(Ab + (r0 + 8) * GST + cb + 8);
            }
            #pragma unroll
            for (int nf = 0; nf < 8; ++nf) {
                const __half* wrow = Wb + (nf * 8 + lr) * GST;
                const uint32_t b0 = ld32s(wrow + cb);
                const uint32_t b1 = ld32s(wrow + cb + 8);
                mma_f16(acc[0][nf], a[0], b0, b1);
                mma_f16(acc[1][nf], a[1], b0, b1);
            }
        }
        if (ch + 2 < nch) stage(ch + 2, (buf + 2) % 3);
        else cp_commit();
        buf = (buf + 1) % 3;
    }
}

__global__ __launch_bounds__(256) void gemm_qkv(
    const float* __restrict__ bq, const float* __restrict__ bk,
    const float* __restrict__ bv)
{
    extern __shared__ char smem[];
    const uint32_t sb = smem_u32(smem);
    const int tid = threadIdx.x;
    const int lane = tid & 31;
    const int w = tid >> 5;
    const int lr = lane >> 2, lc = lane & 3;
    const int rowBase = blockIdx.y * 256;
    const int colBase = blockIdx.x * 64;

    const __half* WT; const float* bias; int colLoc, seg;
    if (colBase < 768)       { WT = g_WqT; bias = bq; colLoc = colBase;        seg = 0; }
    else if (colBase < 1024) { WT = g_WkT; bias = bk; colLoc = colBase - 768;  seg = 1; }
    else                     { WT = g_WvT; bias = bv; colLoc = colBase - 1024; seg = 2; }

    float acc[2][8][4];
    #pragma unroll
    for (int hh = 0; hh < 2; ++hh)
        #pragma unroll
        for (int i = 0; i < 8; ++i)
            #pragma unroll
            for (int j = 0; j < 4; ++j) acc[hh][i][j] = 0.f;

    gemm16_mainloop(sb, smem, g_Xh + (size_t)rowBase * kD,
                    WT + (size_t)colLoc * kD, w, lr, lc, tid, acc);

    const int bb = rowBase / kS;
    const int s0 = rowBase - bb * kS;

    if (seg == 2) {
        __syncthreads();
        __half* T = reinterpret_cast<__half*>(smem);   // [64][TPAD=264]
        #pragma unroll
        for (int hh = 0; hh < 2; ++hh)
            #pragma unroll
            for (int half = 0; half < 2; ++half) {
                const int r = w * 32 + hh * 16 + lr + half * 8;   // s index 0..255
                #pragma unroll
                for (int nf = 0; nf < 8; ++nf) {
                    const int c = nf * 8 + 2 * lc;
                    T[(c + 0) * TPAD + r] = __float2half_rn(acc[hh][nf][half * 2 + 0] + bias[colLoc + c]);
                    T[(c + 1) * TPAD + r] = __float2half_rn(acc[hh][nf][half * 2 + 1] + bias[colLoc + c + 1]);
                }
            }
        __syncthreads();
        const int g = colLoc / kHD;
        __half* base = g_Vh + (size_t)(bb * kGH + g) * kHD * kS;
        #pragma unroll
        for (int j = 0; j < 8; ++j) {
            const int idx = tid + 256 * j;               // 2048 uint4 chunks
            const int hd = idx >> 5, ch8 = (idx & 31) * 8;
            uint4 v = *reinterpret_cast<const uint4*>(T + hd * TPAD + ch8);
            *reinterpret_cast<uint4*>(base + (size_t)hd * kS + s0 + ch8) = v;
        }
    } else {
        __half* out = (seg == 0) ? g_Qh : g_Kh;
        const int heads = (seg == 0) ? kNH : kGH;
        #pragma unroll
        for (int hh = 0; hh < 2; ++hh)
            #pragma unroll
            for (int half = 0; half < 2; ++half) {
                const int s = s0 + w * 32 + hh * 16 + lr + half * 8;
                #pragma unroll
                for (int nf = 0; nf < 8; ++nf) {
                    const int c = colLoc + nf * 8 + 2 * lc;
                    const int h = c / kHD, cc = c - h * kHD;
                    const float v0 = acc[hh][nf][half * 2 + 0] + bias[c];
                    const float v1 = acc[hh][nf][half * 2 + 1] + bias[c + 1];
                    __half* dst = out + ((size_t)(bb * heads + h) * kS + s) * kHD + cc;
                    *reinterpret_cast<uint32_t*>(dst) = pack_f16(v0, v1);
                }
            }
    }
}

__global__ __launch_bounds__(256) void gemm_out(
    const float* __restrict__ bias, float* __restrict__ out)
{
    extern __shared__ char smem[];
    const uint32_t sb = smem_u32(smem);
    const int tid = threadIdx.x;
    const int lane = tid & 31;
    const int w = tid >> 5;
    const int lr = lane >> 2, lc = lane & 3;
    const int rowBase = blockIdx.y * 256;
    const int colBase = blockIdx.x * 64;

    float acc[2][8][4];
    #pragma unroll
    for (int hh = 0; hh < 2; ++hh)
        #pragma unroll
        for (int i = 0; i < 8; ++i)
            #pragma unroll
            for (int j = 0; j < 4; ++j) acc[hh][i][j] = 0.f;

    gemm16_mainloop(sb, smem, g_Oh + (size_t)rowBase * kD,
                    g_WoT + (size_t)colBase * kD, w, lr, lc, tid, acc);

    #pragma unroll
    for (int hh = 0; hh < 2; ++hh)
        #pragma unroll
        for (int half = 0; half < 2; ++half) {
            const int r = rowBase + w * 32 + hh * 16 + lr + half * 8;
            #pragma unroll
            for (int nf = 0; nf < 8; ++nf) {
                const int c = colBase + nf * 8 + 2 * lc;
                float* dst = out + (size_t)r * kD + c;
                dst[0] = acc[hh][nf][half * 2 + 0] + bias[c];
                dst[1] = acc[hh][nf][half * 2 + 1] + bias[c + 1];
            }
        }
}

// ---------------------------------------------------------------------------
// Attention (proven R14): masked-tail skip + global LPT schedule.
// ---------------------------------------------------------------------------
namespace {
constexpr int KST2 = 72;
constexpr int TILE_B = 64 * KST2 * 2;
constexpr int STAGE_B = 2 * TILE_B;
constexpr int SMEM_ATTN = 3 * STAGE_B;         // 55296 B
}

__global__ __launch_bounds__(256, 2) void attn_mma()
{
    extern __shared__ char smem[];
    const uint32_t sb = smem_u32(smem);

    const int tid = threadIdx.x;
    const int lane = tid & 31;
    const int w = tid >> 5;
    const int id = blockIdx.x;
    const int qt = 15 - id / 24;
    const int pair = id % 24;
    const int h = pair % kNH, b = pair / kNH;
    const int g = h / kREP;
    const int lr = lane >> 2, lc = lane & 3;
    const int ktmax = 2 * qt + 2;

    const __half* Qp = g_Qh + ((size_t)(b * kNH + h) * kS + (size_t)qt * 128) * kHD;
    const __half* Kp = g_Kh + (size_t)(b * kGH + g) * kS * kHD;
    const __half* Vp = g_Vh + (size_t)(b * kGH + g) * kHD * kS;

    auto stage_tile = [&](int kt, int s) {
        const __half* Kt = Kp + (size_t)kt * 64 * kHD;
        const __half* Vt = Vp + (size_t)kt * 64;
        const uint32_t kb = sb + s * STAGE_B;
        const uint32_t vb = kb + TILE_B;
        #pragma unroll
        for (int j = 0; j < 2; ++j) {
            const int c = tid + 256 * j;
            const int r = c >> 3, c8 = (c & 7) * 8;
            const uint32_t off = (uint32_t)(r * KST2 + c8) * 2;
            cp16(kb + off, Kt + (size_t)r * kHD + c8);
            cp16(vb + off, Vt + (size_t)r * kS + c8);
        }
        cp_commit();
    };

    stage_tile(0, 0);
    stage_tile(1, 1);

    __half* Qs = reinterpret_cast<__half*>(smem + 2 * STAGE_B);
    #pragma unroll
    for (int j = 0; j < 4; ++j) {
        const int c = tid + 256 * j;
        const int r = c >> 3, c8 = (c & 7) * 8;
        uint4 v = *reinterpret_cast<const uint4*>(Qp + (size_t)r * kHD + c8);
        *reinterpret_cast<uint4*>(Qs + r * KST2 + c8) = v;
    }
    __syncthreads();

    uint32_t qa[4][4];
    {
        const int r0 = w * 16 + lr;
        #pragma unroll
        for (int ks = 0; ks < 4; ++ks) {
            const int cb = ks * 16 + 2 * lc;
            qa[ks][0] = ld32s(Qs + r0 * KST2 + cb);
            qa[ks][1] = ld32s(Qs + (r0 + 8) * KST2 + cb);
            qa[ks][2] = ld32s(Qs + r0 * KST2 + cb + 8);
            qa[ks][3] = ld32s(Qs + (r0 + 8) * KST2 + cb + 8);
        }
    }

    float oacc[8][4];
    #pragma unroll
    for (int i = 0; i < 8; ++i)
        #pragma unroll
        for (int j = 0; j < 4; ++j) oacc[i][j] = 0.f;
    float lsum0 = 0.f, lsum1 = 0.f;
    const int q0 = qt * 128 + w * 16 + lr;

    int buf = 0;
    for (int kt = 0; kt < ktmax; ++kt) {
        cp_wait1();
        __syncthreads();

        const __half* Kb = reinterpret_cast<const __half*>(smem + buf * STAGE_B);
        const __half* Vb = Kb + 64 * KST2;

        #pragma unroll
        for (int sub = 0; sub < 2; ++sub) {
            float sacc[4][4];
            #pragma unroll
            for (int i = 0; i < 4; ++i)
                #pragma unroll
                for (int j = 0; j < 4; ++j) sacc[i][j] = 0.f;

            #pragma unroll
            for (int nf = 0; nf < 4; ++nf) {
                const __half* krow = Kb + (sub * 32 + nf * 8 + lr) * KST2;
                #pragma unroll
                for (int ks = 0; ks < 4; ++ks) {
                    mma_f16(sacc[nf], qa[ks],
                            ld32s(krow + ks * 16 + 2 * lc),
                            ld32s(krow + ks * 16 + 2 * lc + 8));
                }
            }

            uint32_t pa[2][4];
            #pragma unroll
            for (int nf = 0; nf < 4; ++nf) {
                const int colb = kt * 64 + sub * 32 + nf * 8 + 2 * lc;
                const float p0 = (colb     <= q0)     ? __expf(sacc[nf][0] * kScale) : 1.0f;
                const float p1 = (colb + 1 <= q0)     ? __expf(sacc[nf][1] * kScale) : 1.0f;
                const float p2 = (colb     <= q0 + 8) ? __expf(sacc[nf][2] * kScale) : 1.0f;
                const float p3 = (colb + 1 <= q0 + 8) ? __expf(sacc[nf][3] * kScale) : 1.0f;
                lsum0 += p0 + p1;
                lsum1 += p2 + p3;
                const int kk = nf >> 1;
                if ((nf & 1) == 0) {
                    pa[kk][0] = pack_f16(p0, p1);
                    pa[kk][1] = pack_f16(p2, p3);
                } else {
                    pa[kk][2] = pack_f16(p0, p1);
                    pa[kk][3] = pack_f16(p2, p3);
                }
            }

            #pragma unroll
            for (int nd = 0; nd < 8; ++nd) {
                const __half* vrow = Vb + (nd * 8 + lr) * KST2 + sub * 32;
                #pragma unroll
                for (int kk = 0; kk < 2; ++kk) {
                    mma_f16(oacc[nd], pa[kk],
                            ld32s(vrow + kk * 16 + 2 * lc),
                            ld32s(vrow + kk * 16 + 2 * lc + 8));
                }
            }
        }

        if (kt + 2 < ktmax) stage_tile(kt + 2, (buf + 2) % 3);
        else cp_commit();
        buf = (buf + 1) % 3;
    }

    const float* suf = g_Vsuf + ((size_t)(b * kGH + g) * 33 + ktmax) * kHD;
    #pragma unroll
    for (int nd = 0; nd < 8; ++nd) {
        const int hd = nd * 8 + 2 * lc;
        const float s0v = suf[hd], s1v = suf[hd + 1];
        oacc[nd][0] += s0v; oacc[nd][1] += s1v;
        oacc[nd][2] += s0v; oacc[nd][3] += s1v;
    }

    lsum0 += __shfl_xor_sync(0xffffffffu, lsum0, 1);
    lsum0 += __shfl_xor_sync(0xffffffffu, lsum0, 2);
    lsum1 += __shfl_xor_sync(0xffffffffu, lsum1, 1);
    lsum1 += __shfl_xor_sync(0xffffffffu, lsum1, 2);
    const float tail = (float)(kS - ktmax * 64);
    const float inv0 = 1.f / (lsum0 + tail);
    const float inv1 = 1.f / (lsum1 + tail);

    __half* Op = g_Oh + (size_t)(b * kNH + h) * kHD * kS;
    #pragma unroll
    for (int nd = 0; nd < 8; ++nd) {
        const int hd = nd * 8 + 2 * lc;
        Op[(size_t)hd * kS + q0]           = __float2half_rn(oacc[nd][0] * inv0);
        Op[(size_t)(hd + 1) * kS + q0]     = __float2half_rn(oacc[nd][1] * inv0);
        Op[(size_t)hd * kS + q0 + 8]       = __float2half_rn(oacc[nd][2] * inv1);
        Op[(size_t)(hd + 1) * kS + q0 + 8] = __float2half_rn(oacc[nd][3] * inv1);
    }
}

extern "C" void kernel_launch(void* const* d_in, const int* in_sizes, int n_in,
                              void* d_out, int out_size)
{
    (void)in_sizes; (void)n_in; (void)out_size;
    const float* x  = (const float*)d_in[0];
    const float* Wq = (const float*)d_in[2];
    const float* bq = (const float*)d_in[3];
    const float* Wk = (const float*)d_in[4];
    const float* bk = (const float*)d_in[5];
    const float* Wv = (const float*)d_in[6];
    const float* bv = (const float*)d_in[7];
    const float* Wo = (const float*)d_in[8];
    const float* bo = (const float*)d_in[9];
    float* out = (float*)d_out;

    cudaFuncSetAttribute(attn_mma, cudaFuncAttributeMaxDynamicSharedMemorySize, SMEM_ATTN);
    cudaFuncSetAttribute(gemm_qkv, cudaFuncAttributeMaxDynamicSharedMemorySize, SMEM_GEMM);
    cudaFuncSetAttribute(gemm_out, cudaFuncAttributeMaxDynamicSharedMemorySize, SMEM_GEMM);

    convert_all<<<3072 + 1536, 256>>>(x, Wq, Wk, Wv, Wo);

    gemm_qkv<<<dim3(1280 / 64, (kB * kS) / 256), 256, SMEM_GEMM>>>(bq, bk, bv);

    vsuf_kernel<<<64, 256>>>();

    attn_mma<<<kS / 128 * kNH * kB, 256, SMEM_ATTN>>>();

    gemm_out<<<dim3(kD / 64, (kB * kS) / 256), 256, SMEM_GEMM>>>(bo, out);
}

// round 16
// speedup vs baseline: 1.0845x; 1.0845x over previous
#include <cuda_runtime.h>
#include <cuda_fp16.h>
#include <cstdint>

// GroupQuerySelfAttention: B=2, S=2048, D=768, NH=12, GH=4 (rep=3), HD=64
// MASK_FILL = -1e-9 => masked p == exp(-1e-9) == 1.0f exactly; V suffix sums
// skip ~half the attention tiles. R16: attention row-sums computed via an
// extra mma with B==1.0h (replaces 32 FMA/tile + final shuffles) and the
// mask compare runs only on the 2 diagonal tiles. GEMMs reverted to the
// proven R14 128-row config (R15's 256-row tile lost to wave quantization).
// Buggy merge == attention out stored [B,NH,HD,S].

namespace {
constexpr int kB  = 2;
constexpr int kS  = 2048;
constexpr int kD  = 768;
constexpr int kNH = 12;
constexpr int kGH = 4;
constexpr int kHD = 64;
constexpr int kREP = 3;
constexpr float kScale = 0.125f;
}

__device__ __half g_Xh [(size_t)kB * kS * kD];
__device__ __half g_WqT[(size_t)kD * kD];
__device__ __half g_WkT[(size_t)(kGH * kHD) * kD];
__device__ __half g_WvT[(size_t)(kGH * kHD) * kD];
__device__ __half g_WoT[(size_t)kD * kD];
__device__ __half g_Qh [(size_t)kB * kNH * kS * kHD];
__device__ __half g_Kh [(size_t)kB * kGH * kS * kHD];
__device__ __half g_Vh [(size_t)kB * kGH * kHD * kS];  // [b, g, hd, s]
__device__ __half g_Oh [(size_t)kB * kNH * kHD * kS];  // [b, h, hd, q]
__device__ float  g_Vsuf[(size_t)kB * kGH * 33 * kHD];

// ---------------------------------------------------------------------------
__device__ __forceinline__ void mma_f16(float* d, const uint32_t* a,
                                        uint32_t b0, uint32_t b1) {
    asm volatile(
        "mma.sync.aligned.m16n8k16.row.col.f32.f16.f16.f32 "
        "{%0,%1,%2,%3}, {%4,%5,%6,%7}, {%8,%9}, {%0,%1,%2,%3};"
        : "+f"(d[0]), "+f"(d[1]), "+f"(d[2]), "+f"(d[3])
        : "r"(a[0]), "r"(a[1]), "r"(a[2]), "r"(a[3]), "r"(b0), "r"(b1));
}
__device__ __forceinline__ uint32_t pack_f16(float lo, float hi) {
    uint32_t r;
    asm("cvt.rn.f16x2.f32 %0, %1, %2;" : "=r"(r) : "f"(hi), "f"(lo));
    return r;
}
__device__ __forceinline__ uint32_t smem_u32(const void* p) {
    uint32_t a;
    asm("{ .reg .u64 t; cvta.to.shared.u64 t, %1; cvt.u32.u64 %0, t; }"
        : "=r"(a) : "l"(p));
    return a;
}
__device__ __forceinline__ void cp16(uint32_t dst, const void* src) {
    asm volatile("cp.async.cg.shared.global [%0], [%1], 16;"
                 :: "r"(dst), "l"(src) : "memory");
}
__device__ __forceinline__ void cp_commit() {
    asm volatile("cp.async.commit_group;" ::: "memory");
}
__device__ __forceinline__ void cp_wait1() {
    asm volatile("cp.async.wait_group 1;" ::: "memory");
}
__device__ __forceinline__ uint32_t ld32s(const __half* p) {
    return *reinterpret_cast<const uint32_t*>(p);
}

// ---------------------------------------------------------------------------
// Merged prep: blocks [0,3072) convert x; [3072,4608) transpose+convert W.
// ---------------------------------------------------------------------------
__global__ __launch_bounds__(256) void convert_all(
    const float* __restrict__ x,
    const float* __restrict__ Wq, const float* __restrict__ Wk,
    const float* __restrict__ Wv, const float* __restrict__ Wo)
{
    if (blockIdx.x < 3072) {
        const int idx = blockIdx.x * 256 + threadIdx.x;
        float4 v = reinterpret_cast<const float4*>(x)[idx];
        uint2 p;
        p.x = pack_f16(v.x, v.y);
        p.y = pack_f16(v.z, v.w);
        reinterpret_cast<uint2*>(g_Xh)[idx] = p;
        return;
    }
    __shared__ float t[32][33];
    const int wb = blockIdx.x - 3072;
    const int c0 = (wb & 63) * 32;
    const int k0 = (wb >> 6) * 32;
    const float* W; __half* dst; int Nw, cl;
    if (c0 < 768)       { W = Wq; dst = g_WqT; Nw = 768; cl = c0; }
    else if (c0 < 1024) { W = Wk; dst = g_WkT; Nw = 256; cl = c0 - 768; }
    else if (c0 < 1280) { W = Wv; dst = g_WvT; Nw = 256; cl = c0 - 1024; }
    else                { W = Wo; dst = g_WoT; Nw = 768; cl = c0 - 1280; }
    const int tx = threadIdx.x & 31, ty = threadIdx.x >> 5;
    #pragma unroll
    for (int j = 0; j < 4; ++j)
        t[ty + j * 8][tx] = W[(size_t)(k0 + ty + j * 8) * Nw + cl + tx];
    __syncthreads();
    #pragma unroll
    for (int j = 0; j < 4; ++j) {
        const int n = ty + j * 8;
        dst[(size_t)(cl + n) * kD + k0 + tx] = __float2half_rn(t[tx][n]);
    }
}

// V suffix tile-colsum (proven R14)
__global__ __launch_bounds__(256) void vsuf_kernel()
{
    const int warp = threadIdx.x >> 5, lane = threadIdx.x & 31;
    const int bg = blockIdx.x >> 3;
    const int hd = (blockIdx.x & 7) * 8 + warp;
    const __half* row = g_Vh + ((size_t)bg * kHD + hd) * kS + lane * 64;

    float s = 0.f;
    #pragma unroll
    for (int i = 0; i < 8; ++i) {
        const uint4 v = *reinterpret_cast<const uint4*>(row + i * 8);
        const __half2* h2 = reinterpret_cast<const __half2*>(&v);
        #pragma unroll
        for (int j = 0; j < 4; ++j) {
            const float2 f = __half22float2(h2[j]);
            s += f.x + f.y;
        }
    }
    #pragma unroll
    for (int off = 1; off < 32; off <<= 1) {
        const float up = __shfl_down_sync(0xffffffffu, s, off);
        if (lane + off < 32) s += up;
    }
    float* dst = g_Vsuf + (size_t)bg * 33 * kHD + hd;
    dst[(size_t)lane * kHD] = s;
    if (lane == 0) dst[(size_t)32 * kHD] = 0.f;
}

// ---------------------------------------------------------------------------
// Pipelined f16 GEMM core — R14 config (128m x 64n CTA, 3-4 CTAs/SM)
// ---------------------------------------------------------------------------
namespace {
constexpr int GST = 40;
constexpr int GA_B = 128 * GST * 2;
constexpr int GW_B = 64 * GST * 2;
constexpr int GSTAGE_B = GA_B + GW_B;          // 15360 B
constexpr int SMEM_GEMM = 3 * GSTAGE_B;        // 46080 B
constexpr int TPAD = 136;
}

__device__ __forceinline__ void gemm16_mainloop(
    uint32_t sb, const char* smem,
    const __half* __restrict__ Arow, const __half* __restrict__ Wrow,
    int w, int lr, int lc, int tid, float (&acc)[8][4])
{
    auto stage = [&](int ch, int s) {
        const int k0 = ch * 32;
        const uint32_t ab = sb + s * GSTAGE_B;
        const uint32_t wb = ab + GA_B;
        #pragma unroll
        for (int j = 0; j < 2; ++j) {
            const int idx = tid + 256 * j;
            const int r = idx >> 2, c4 = idx & 3;
            cp16(ab + (uint32_t)(r * GST + c4 * 8) * 2,
                 Arow + (size_t)r * kD + k0 + c4 * 8);
        }
        {
            const int r = tid >> 2, c4 = tid & 3;
            cp16(wb + (uint32_t)(r * GST + c4 * 8) * 2,
                 Wrow + (size_t)r * kD + k0 + c4 * 8);
        }
        cp_commit();
    };

    stage(0, 0);
    stage(1, 1);

    const int r0 = w * 16 + lr;
    const int nch = kD / 32;
    int buf = 0;
    for (int ch = 0; ch < nch; ++ch) {
        cp_wait1();
        __syncthreads();
        const __half* Ab = reinterpret_cast<const __half*>(smem + buf * GSTAGE_B);
        const __half* Wb = Ab + 128 * GST;
        #pragma unroll
        for (int ks = 0; ks < 2; ++ks) {
            const int cb = ks * 16 + 2 * lc;
            uint32_t a[4];
            a[0] = ld32s(Ab + r0 * GST + cb);
            a[1] = ld32s(Ab + (r0 + 8) * GST + cb);
            a[2] = ld32s(Ab + r0 * GST + cb + 8);
            a[3] = ld32s(Ab + (r0 + 8) * GST + cb + 8);
            #pragma unroll
            for (int nf = 0; nf < 8; ++nf) {
                const __half* wrow = Wb + (nf * 8 + lr) * GST;
                mma_f16(acc[nf], a, ld32s(wrow + cb), ld32s(wrow + cb + 8));
            }
        }
        if (ch + 2 < nch) stage(ch + 2, (buf + 2) % 3);
        else cp_commit();
        buf = (buf + 1) % 3;
    }
}

__global__ __launch_bounds__(256) void gemm_qkv(
    const float* __restrict__ bq, const float* __restrict__ bk,
    const float* __restrict__ bv)
{
    extern __shared__ char smem[];
    const uint32_t sb = smem_u32(smem);
    const int tid = threadIdx.x;
    const int lane = tid & 31;
    const int w = tid >> 5;
    const int lr = lane >> 2, lc = lane & 3;
    const int rowBase = blockIdx.y * 128;
    const int colBase = blockIdx.x * 64;

    const __half* WT; const float* bias; int colLoc, seg;
    if (colBase < 768)       { WT = g_WqT; bias = bq; colLoc = colBase;        seg = 0; }
    else if (colBase < 1024) { WT = g_WkT; bias = bk; colLoc = colBase - 768;  seg = 1; }
    else                     { WT = g_WvT; bias = bv; colLoc = colBase - 1024; seg = 2; }

    float acc[8][4];
    #pragma unroll
    for (int i = 0; i < 8; ++i)
        #pragma unroll
        for (int j = 0; j < 4; ++j) acc[i][j] = 0.f;

    gemm16_mainloop(sb, smem, g_Xh + (size_t)rowBase * kD,
                    WT + (size_t)colLoc * kD, w, lr, lc, tid, acc);

    const int bb = rowBase / kS;
    const int s0 = rowBase - bb * kS;

    if (seg == 2) {
        __syncthreads();
        __half* T = reinterpret_cast<__half*>(smem);   // [64][TPAD]
        #pragma unroll
        for (int half = 0; half < 2; ++half) {
            const int r = w * 16 + lr + half * 8;
            #pragma unroll
            for (int nf = 0; nf < 8; ++nf) {
                const int c = nf * 8 + 2 * lc;
                T[(c + 0) * TPAD + r] = __float2half_rn(acc[nf][half * 2 + 0] + bias[colLoc + c]);
                T[(c + 1) * TPAD + r] = __float2half_rn(acc[nf][half * 2 + 1] + bias[colLoc + c + 1]);
            }
        }
        __syncthreads();
        const int g = colLoc / kHD;
        __half* base = g_Vh + (size_t)(bb * kGH + g) * kHD * kS;
        #pragma unroll
        for (int j = 0; j < 4; ++j) {
            const int idx = tid + 256 * j;
            const int hd = idx >> 4, ch8 = (idx & 15) * 8;
            uint4 v = *reinterpret_cast<const uint4*>(T + hd * TPAD + ch8);
            *reinterpret_cast<uint4*>(base + (size_t)hd * kS + s0 + ch8) = v;
        }
    } else {
        __half* out = (seg == 0) ? g_Qh : g_Kh;
        const int heads = (seg == 0) ? kNH : kGH;
        #pragma unroll
        for (int half = 0; half < 2; ++half) {
            const int s = s0 + w * 16 + lr + half * 8;
            #pragma unroll
            for (int nf = 0; nf < 8; ++nf) {
                const int c = colLoc + nf * 8 + 2 * lc;
                const int h = c / kHD, cc = c - h * kHD;
                const float v0 = acc[nf][half * 2 + 0] + bias[c];
                const float v1 = acc[nf][half * 2 + 1] + bias[c + 1];
                __half* dst = out + ((size_t)(bb * heads + h) * kS + s) * kHD + cc;
                *reinterpret_cast<uint32_t*>(dst) = pack_f16(v0, v1);
            }
        }
    }
}

__global__ __launch_bounds__(256) void gemm_out(
    const float* __restrict__ bias, float* __restrict__ out)
{
    extern __shared__ char smem[];
    const uint32_t sb = smem_u32(smem);
    const int tid = threadIdx.x;
    const int lane = tid & 31;
    const int w = tid >> 5;
    const int lr = lane >> 2, lc = lane & 3;
    const int rowBase = blockIdx.y * 128;
    const int colBase = blockIdx.x * 64;

    float acc[8][4];
    #pragma unroll
    for (int i = 0; i < 8; ++i)
        #pragma unroll
        for (int j = 0; j < 4; ++j) acc[i][j] = 0.f;

    gemm16_mainloop(sb, smem, g_Oh + (size_t)rowBase * kD,
                    g_WoT + (size_t)colBase * kD, w, lr, lc, tid, acc);

    #pragma unroll
    for (int half = 0; half < 2; ++half) {
        const int r = rowBase + w * 16 + lr + half * 8;
        #pragma unroll
        for (int nf = 0; nf < 8; ++nf) {
            const int c = colBase + nf * 8 + 2 * lc;
            float* dst = out + (size_t)r * kD + c;
            dst[0] = acc[nf][half * 2 + 0] + bias[c];
            dst[1] = acc[nf][half * 2 + 1] + bias[c + 1];
        }
    }
}

// ---------------------------------------------------------------------------
// Attention: masked-tail skip + LPT + ones-mma rowsum + diag-only masking.
// ---------------------------------------------------------------------------
namespace {
constexpr int KST2 = 72;
constexpr int TILE_B = 64 * KST2 * 2;
constexpr int STAGE_B = 2 * TILE_B;
constexpr int SMEM_ATTN = 3 * STAGE_B;         // 55296 B
constexpr uint32_t ONE2 = 0x3C003C00u;         // f16x2 {1.0, 1.0}
}

__global__ __launch_bounds__(256, 2) void attn_mma()
{
    extern __shared__ char smem[];
    const uint32_t sb = smem_u32(smem);

    const int tid = threadIdx.x;
    const int lane = tid & 31;
    const int w = tid >> 5;
    const int id = blockIdx.x;
    const int qt = 15 - id / 24;               // global LPT
    const int pair = id % 24;
    const int h = pair % kNH, b = pair / kNH;
    const int g = h / kREP;
    const int lr = lane >> 2, lc = lane & 3;
    const int ktmax = 2 * qt + 2;

    const __half* Qp = g_Qh + ((size_t)(b * kNH + h) * kS + (size_t)qt * 128) * kHD;
    const __half* Kp = g_Kh + (size_t)(b * kGH + g) * kS * kHD;
    const __half* Vp = g_Vh + (size_t)(b * kGH + g) * kHD * kS;

    auto stage_tile = [&](int kt, int s) {
        const __half* Kt = Kp + (size_t)kt * 64 * kHD;
        const __half* Vt = Vp + (size_t)kt * 64;
        const uint32_t kb = sb + s * STAGE_B;
        const uint32_t vb = kb + TILE_B;
        #pragma unroll
        for (int j = 0; j < 2; ++j) {
            const int c = tid + 256 * j;
            const int r = c >> 3, c8 = (c & 7) * 8;
            const uint32_t off = (uint32_t)(r * KST2 + c8) * 2;
            cp16(kb + off, Kt + (size_t)r * kHD + c8);
            cp16(vb + off, Vt + (size_t)r * kS + c8);
        }
        cp_commit();
    };

    stage_tile(0, 0);
    stage_tile(1, 1);

    __half* Qs = reinterpret_cast<__half*>(smem + 2 * STAGE_B);
    #pragma unroll
    for (int j = 0; j < 4; ++j) {
        const int c = tid + 256 * j;
        const int r = c >> 3, c8 = (c & 7) * 8;
        uint4 v = *reinterpret_cast<const uint4*>(Qp + (size_t)r * kHD + c8);
        *reinterpret_cast<uint4*>(Qs + r * KST2 + c8) = v;
    }
    __syncthreads();

    uint32_t qa[4][4];
    {
        const int r0 = w * 16 + lr;
        #pragma unroll
        for (int ks = 0; ks < 4; ++ks) {
            const int cb = ks * 16 + 2 * lc;
            qa[ks][0] = ld32s(Qs + r0 * KST2 + cb);
            qa[ks][1] = ld32s(Qs + (r0 + 8) * KST2 + cb);
            qa[ks][2] = ld32s(Qs + r0 * KST2 + cb + 8);
            qa[ks][3] = ld32s(Qs + (r0 + 8) * KST2 + cb + 8);
        }
    }

    float oacc[8][4];
    #pragma unroll
    for (int i = 0; i < 8; ++i)
        #pragma unroll
        for (int j = 0; j < 4; ++j) oacc[i][j] = 0.f;
    float lacc[4] = {0.f, 0.f, 0.f, 0.f};       // rowsum via ones-mma
    const int q0 = qt * 128 + w * 16 + lr;

    int buf = 0;
    for (int kt = 0; kt < ktmax; ++kt) {
        cp_wait1();
        __syncthreads();

        const __half* Kb = reinterpret_cast<const __half*>(smem + buf * STAGE_B);
        const __half* Vb = Kb + 64 * KST2;
        const bool diag = (kt >= 2 * qt);       // warp-uniform

        #pragma unroll
        for (int sub = 0; sub < 2; ++sub) {
            float sacc[4][4];
            #pragma unroll
            for (int i = 0; i < 4; ++i)
                #pragma unroll
                for (int j = 0; j < 4; ++j) sacc[i][j] = 0.f;

            #pragma unroll
            for (int nf = 0; nf < 4; ++nf) {
                const __half* krow = Kb + (sub * 32 + nf * 8 + lr) * KST2;
                #pragma unroll
                for (int ks = 0; ks < 4; ++ks) {
                    mma_f16(sacc[nf], qa[ks],
                            ld32s(krow + ks * 16 + 2 * lc),
                            ld32s(krow + ks * 16 + 2 * lc + 8));
                }
            }

            uint32_t pa[2][4];
            if (diag) {
                #pragma unroll
                for (int nf = 0; nf < 4; ++nf) {
                    const int colb = kt * 64 + sub * 32 + nf * 8 + 2 * lc;
                    const float p0 = (colb     <= q0)     ? __expf(sacc[nf][0] * kScale) : 1.0f;
                    const float p1 = (colb + 1 <= q0)     ? __expf(sacc[nf][1] * kScale) : 1.0f;
                    const float p2 = (colb     <= q0 + 8) ? __expf(sacc[nf][2] * kScale) : 1.0f;
                    const float p3 = (colb + 1 <= q0 + 8) ? __expf(sacc[nf][3] * kScale) : 1.0f;
                    const int kk = nf >> 1;
                    if ((nf & 1) == 0) {
                        pa[kk][0] = pack_f16(p0, p1);
                        pa[kk][1] = pack_f16(p2, p3);
                    } else {
                        pa[kk][2] = pack_f16(p0, p1);
                        pa[kk][3] = pack_f16(p2, p3);
                    }
                }
            } else {
                #pragma unroll
                for (int nf = 0; nf < 4; ++nf) {
                    const float p0 = __expf(sacc[nf][0] * kScale);
                    const float p1 = __expf(sacc[nf][1] * kScale);
                    const float p2 = __expf(sacc[nf][2] * kScale);
                    const float p3 = __expf(sacc[nf][3] * kScale);
                    const int kk = nf >> 1;
                    if ((nf & 1) == 0) {
                        pa[kk][0] = pack_f16(p0, p1);
                        pa[kk][1] = pack_f16(p2, p3);
                    } else {
                        pa[kk][2] = pack_f16(p0, p1);
                        pa[kk][3] = pack_f16(p2, p3);
                    }
                }
            }

            // PV + rowsum (B = ones)
            #pragma unroll
            for (int kk = 0; kk < 2; ++kk)
                mma_f16(lacc, pa[kk], ONE2, ONE2);
            #pragma unroll
            for (int nd = 0; nd < 8; ++nd) {
                const __half* vrow = Vb + (nd * 8 + lr) * KST2 + sub * 32;
                #pragma unroll
                for (int kk = 0; kk < 2; ++kk) {
                    mma_f16(oacc[nd], pa[kk],
                            ld32s(vrow + kk * 16 + 2 * lc),
                            ld32s(vrow + kk * 16 + 2 * lc + 8));
                }
            }
        }

        if (kt + 2 < ktmax) stage_tile(kt + 2, (buf + 2) % 3);
        else cp_commit();
        buf = (buf + 1) % 3;
    }

    // fully-masked suffix: O += colsum(V[ktmax*64:]); lsum += tail count
    const float* suf = g_Vsuf + ((size_t)(b * kGH + g) * 33 + ktmax) * kHD;
    #pragma unroll
    for (int nd = 0; nd < 8; ++nd) {
        const int hd = nd * 8 + 2 * lc;
        const float s0v = suf[hd], s1v = suf[hd + 1];
        oacc[nd][0] += s0v; oacc[nd][1] += s1v;
        oacc[nd][2] += s0v; oacc[nd][3] += s1v;
    }

    const float tail = (float)(kS - ktmax * 64);
    const float inv0 = 1.f / (lacc[0] + tail);   // complete row sums (mma
    const float inv1 = 1.f / (lacc[2] + tail);   // reduced over full k)

    __half* Op = g_Oh + (size_t)(b * kNH + h) * kHD * kS;
    #pragma unroll
    for (int nd = 0; nd < 8; ++nd) {
        const int hd = nd * 8 + 2 * lc;
        Op[(size_t)hd * kS + q0]           = __float2half_rn(oacc[nd][0] * inv0);
        Op[(size_t)(hd + 1) * kS + q0]     = __float2half_rn(oacc[nd][1] * inv0);
        Op[(size_t)hd * kS + q0 + 8]       = __float2half_rn(oacc[nd][2] * inv1);
        Op[(size_t)(hd + 1) * kS + q0 + 8] = __float2half_rn(oacc[nd][3] * inv1);
    }
}

extern "C" void kernel_launch(void* const* d_in, const int* in_sizes, int n_in,
                              void* d_out, int out_size)
{
    (void)in_sizes; (void)n_in; (void)out_size;
    const float* x  = (const float*)d_in[0];
    const float* Wq = (const float*)d_in[2];
    const float* bq = (const float*)d_in[3];
    const float* Wk = (const float*)d_in[4];
    const float* bk = (const float*)d_in[5];
    const float* Wv = (const float*)d_in[6];
    const float* bv = (const float*)d_in[7];
    const float* Wo = (const float*)d_in[8];
    const float* bo = (const float*)d_in[9];
    float* out = (float*)d_out;

    cudaFuncSetAttribute(attn_mma, cudaFuncAttributeMaxDynamicSharedMemorySize, SMEM_ATTN);
    cudaFuncSetAttribute(gemm_qkv, cudaFuncAttributeMaxDynamicSharedMemorySize, SMEM_GEMM);
    cudaFuncSetAttribute(gemm_out, cudaFuncAttributeMaxDynamicSharedMemorySize, SMEM_GEMM);

    convert_all<<<3072 + 1536, 256>>>(x, Wq, Wk, Wv, Wo);

    gemm_qkv<<<dim3(1280 / 64, (kB * kS) / 128), 256, SMEM_GEMM>>>(bq, bk, bv);

    vsuf_kernel<<<64, 256>>>();

    attn_mma<<<kS / 128 * kNH * kB, 256, SMEM_ATTN>>>();

    gemm_out<<<dim3(kD / 64, (kB * kS) / 128), 256, SMEM_GEMM>>>(bo, out);
}

// round 17
// speedup vs baseline: 1.0990x; 1.0135x over previous
#include <cuda_runtime.h>
#include <cuda_fp16.h>
#include <cstdint>

// GroupQuerySelfAttention: B=2, S=2048, D=768, NH=12, GH=4 (rep=3), HD=64
// MASK_FILL = -1e-9 => masked p == exp(-1e-9) == 1.0f exactly; V suffix sums
// skip ~half the attention tiles. R17: attention processes 128-key tiles per
// pipeline stage (half the barriers, 4 independent sub-blocks of ILP each),
// exp via ex2.approx with folded scale*log2e. GEMMs: proven R14/R16 config.
// Buggy merge == attention out stored [B,NH,HD,S].

namespace {
constexpr int kB  = 2;
constexpr int kS  = 2048;
constexpr int kD  = 768;
constexpr int kNH = 12;
constexpr int kGH = 4;
constexpr int kHD = 64;
constexpr int kREP = 3;
constexpr float kScaleL2 = 0.125f * 1.44269504f;   // scale * log2(e)
}

__device__ __half g_Xh [(size_t)kB * kS * kD];
__device__ __half g_WqT[(size_t)kD * kD];
__device__ __half g_WkT[(size_t)(kGH * kHD) * kD];
__device__ __half g_WvT[(size_t)(kGH * kHD) * kD];
__device__ __half g_WoT[(size_t)kD * kD];
__device__ __half g_Qh [(size_t)kB * kNH * kS * kHD];
__device__ __half g_Kh [(size_t)kB * kGH * kS * kHD];
__device__ __half g_Vh [(size_t)kB * kGH * kHD * kS];  // [b, g, hd, s]
__device__ __half g_Oh [(size_t)kB * kNH * kHD * kS];  // [b, h, hd, q]
__device__ float  g_Vsuf[(size_t)kB * kGH * 33 * kHD];

// ---------------------------------------------------------------------------
__device__ __forceinline__ void mma_f16(float* d, const uint32_t* a,
                                        uint32_t b0, uint32_t b1) {
    asm volatile(
        "mma.sync.aligned.m16n8k16.row.col.f32.f16.f16.f32 "
        "{%0,%1,%2,%3}, {%4,%5,%6,%7}, {%8,%9}, {%0,%1,%2,%3};"
        : "+f"(d[0]), "+f"(d[1]), "+f"(d[2]), "+f"(d[3])
        : "r"(a[0]), "r"(a[1]), "r"(a[2]), "r"(a[3]), "r"(b0), "r"(b1));
}
__device__ __forceinline__ uint32_t pack_f16(float lo, float hi) {
    uint32_t r;
    asm("cvt.rn.f16x2.f32 %0, %1, %2;" : "=r"(r) : "f"(hi), "f"(lo));
    return r;
}
__device__ __forceinline__ float ex2(float x) {
    float r;
    asm("ex2.approx.f32 %0, %1;" : "=f"(r) : "f"(x));
    return r;
}
__device__ __forceinline__ uint32_t smem_u32(const void* p) {
    uint32_t a;
    asm("{ .reg .u64 t; cvta.to.shared.u64 t, %1; cvt.u32.u64 %0, t; }"
        : "=r"(a) : "l"(p));
    return a;
}
__device__ __forceinline__ void cp16(uint32_t dst, const void* src) {
    asm volatile("cp.async.cg.shared.global [%0], [%1], 16;"
                 :: "r"(dst), "l"(src) : "memory");
}
__device__ __forceinline__ void cp_commit() {
    asm volatile("cp.async.commit_group;" ::: "memory");
}
__device__ __forceinline__ void cp_wait1() {
    asm volatile("cp.async.wait_group 1;" ::: "memory");
}
__device__ __forceinline__ uint32_t ld32s(const __half* p) {
    return *reinterpret_cast<const uint32_t*>(p);
}

// ---------------------------------------------------------------------------
// Merged prep: blocks [0,3072) convert x; [3072,4608) transpose+convert W.
// ---------------------------------------------------------------------------
__global__ __launch_bounds__(256) void convert_all(
    const float* __restrict__ x,
    const float* __restrict__ Wq, const float* __restrict__ Wk,
    const float* __restrict__ Wv, const float* __restrict__ Wo)
{
    if (blockIdx.x < 3072) {
        const int idx = blockIdx.x * 256 + threadIdx.x;
        float4 v = reinterpret_cast<const float4*>(x)[idx];
        uint2 p;
        p.x = pack_f16(v.x, v.y);
        p.y = pack_f16(v.z, v.w);
        reinterpret_cast<uint2*>(g_Xh)[idx] = p;
        return;
    }
    __shared__ float t[32][33];
    const int wb = blockIdx.x - 3072;
    const int c0 = (wb & 63) * 32;
    const int k0 = (wb >> 6) * 32;
    const float* W; __half* dst; int Nw, cl;
    if (c0 < 768)       { W = Wq; dst = g_WqT; Nw = 768; cl = c0; }
    else if (c0 < 1024) { W = Wk; dst = g_WkT; Nw = 256; cl = c0 - 768; }
    else if (c0 < 1280) { W = Wv; dst = g_WvT; Nw = 256; cl = c0 - 1024; }
    else                { W = Wo; dst = g_WoT; Nw = 768; cl = c0 - 1280; }
    const int tx = threadIdx.x & 31, ty = threadIdx.x >> 5;
    #pragma unroll
    for (int j = 0; j < 4; ++j)
        t[ty + j * 8][tx] = W[(size_t)(k0 + ty + j * 8) * Nw + cl + tx];
    __syncthreads();
    #pragma unroll
    for (int j = 0; j < 4; ++j) {
        const int n = ty + j * 8;
        dst[(size_t)(cl + n) * kD + k0 + tx] = __float2half_rn(t[tx][n]);
    }
}

// V suffix tile-colsum (proven R14)
__global__ __launch_bounds__(256) void vsuf_kernel()
{
    const int warp = threadIdx.x >> 5, lane = threadIdx.x & 31;
    const int bg = blockIdx.x >> 3;
    const int hd = (blockIdx.x & 7) * 8 + warp;
    const __half* row = g_Vh + ((size_t)bg * kHD + hd) * kS + lane * 64;

    float s = 0.f;
    #pragma unroll
    for (int i = 0; i < 8; ++i) {
        const uint4 v = *reinterpret_cast<const uint4*>(row + i * 8);
        const __half2* h2 = reinterpret_cast<const __half2*>(&v);
        #pragma unroll
        for (int j = 0; j < 4; ++j) {
            const float2 f = __half22float2(h2[j]);
            s += f.x + f.y;
        }
    }
    #pragma unroll
    for (int off = 1; off < 32; off <<= 1) {
        const float up = __shfl_down_sync(0xffffffffu, s, off);
        if (lane + off < 32) s += up;
    }
    float* dst = g_Vsuf + (size_t)bg * 33 * kHD + hd;
    dst[(size_t)lane * kHD] = s;
    if (lane == 0) dst[(size_t)32 * kHD] = 0.f;
}

// ---------------------------------------------------------------------------
// Pipelined f16 GEMM core — proven R14/R16 config (128m x 64n CTA)
// ---------------------------------------------------------------------------
namespace {
constexpr int GST = 40;
constexpr int GA_B = 128 * GST * 2;
constexpr int GW_B = 64 * GST * 2;
constexpr int GSTAGE_B = GA_B + GW_B;          // 15360 B
constexpr int SMEM_GEMM = 3 * GSTAGE_B;        // 46080 B
constexpr int TPAD = 136;
}

__device__ __forceinline__ void gemm16_mainloop(
    uint32_t sb, const char* smem,
    const __half* __restrict__ Arow, const __half* __restrict__ Wrow,
    int w, int lr, int lc, int tid, float (&acc)[8][4])
{
    auto stage = [&](int ch, int s) {
        const int k0 = ch * 32;
        const uint32_t ab = sb + s * GSTAGE_B;
        const uint32_t wb = ab + GA_B;
        #pragma unroll
        for (int j = 0; j < 2; ++j) {
            const int idx = tid + 256 * j;
            const int r = idx >> 2, c4 = idx & 3;
            cp16(ab + (uint32_t)(r * GST + c4 * 8) * 2,
                 Arow + (size_t)r * kD + k0 + c4 * 8);
        }
        {
            const int r = tid >> 2, c4 = tid & 3;
            cp16(wb + (uint32_t)(r * GST + c4 * 8) * 2,
                 Wrow + (size_t)r * kD + k0 + c4 * 8);
        }
        cp_commit();
    };

    stage(0, 0);
    stage(1, 1);

    const int r0 = w * 16 + lr;
    const int nch = kD / 32;
    int buf = 0;
    for (int ch = 0; ch < nch; ++ch) {
        cp_wait1();
        __syncthreads();
        const __half* Ab = reinterpret_cast<const __half*>(smem + buf * GSTAGE_B);
        const __half* Wb = Ab + 128 * GST;
        #pragma unroll
        for (int ks = 0; ks < 2; ++ks) {
            const int cb = ks * 16 + 2 * lc;
            uint32_t a[4];
            a[0] = ld32s(Ab + r0 * GST + cb);
            a[1] = ld32s(Ab + (r0 + 8) * GST + cb);
            a[2] = ld32s(Ab + r0 * GST + cb + 8);
            a[3] = ld32s(Ab + (r0 + 8) * GST + cb + 8);
            #pragma unroll
            for (int nf = 0; nf < 8; ++nf) {
                const __half* wrow = Wb + (nf * 8 + lr) * GST;
                mma_f16(acc[nf], a, ld32s(wrow + cb), ld32s(wrow + cb + 8));
            }
        }
        if (ch + 2 < nch) stage(ch + 2, (buf + 2) % 3);
        else cp_commit();
        buf = (buf + 1) % 3;
    }
}

__global__ __launch_bounds__(256) void gemm_qkv(
    const float* __restrict__ bq, const float* __restrict__ bk,
    const float* __restrict__ bv)
{
    extern __shared__ char smem[];
    const uint32_t sb = smem_u32(smem);
    const int tid = threadIdx.x;
    const int lane = tid & 31;
    const int w = tid >> 5;
    const int lr = lane >> 2, lc = lane & 3;
    const int rowBase = blockIdx.y * 128;
    const int colBase = blockIdx.x * 64;

    const __half* WT; const float* bias; int colLoc, seg;
    if (colBase < 768)       { WT = g_WqT; bias = bq; colLoc = colBase;        seg = 0; }
    else if (colBase < 1024) { WT = g_WkT; bias = bk; colLoc = colBase - 768;  seg = 1; }
    else                     { WT = g_WvT; bias = bv; colLoc = colBase - 1024; seg = 2; }

    float acc[8][4];
    #pragma unroll
    for (int i = 0; i < 8; ++i)
        #pragma unroll
        for (int j = 0; j < 4; ++j) acc[i][j] = 0.f;

    gemm16_mainloop(sb, smem, g_Xh + (size_t)rowBase * kD,
                    WT + (size_t)colLoc * kD, w, lr, lc, tid, acc);

    const int bb = rowBase / kS;
    const int s0 = rowBase - bb * kS;

    if (seg == 2) {
        __syncthreads();
        __half* T = reinterpret_cast<__half*>(smem);   // [64][TPAD]
        #pragma unroll
        for (int half = 0; half < 2; ++half) {
            const int r = w * 16 + lr + half * 8;
            #pragma unroll
            for (int nf = 0; nf < 8; ++nf) {
                const int c = nf * 8 + 2 * lc;
                T[(c + 0) * TPAD + r] = __float2half_rn(acc[nf][half * 2 + 0] + bias[colLoc + c]);
                T[(c + 1) * TPAD + r] = __float2half_rn(acc[nf][half * 2 + 1] + bias[colLoc + c + 1]);
            }
        }
        __syncthreads();
        const int g = colLoc / kHD;
        __half* base = g_Vh + (size_t)(bb * kGH + g) * kHD * kS;
        #pragma unroll
        for (int j = 0; j < 4; ++j) {
            const int idx = tid + 256 * j;
            const int hd = idx >> 4, ch8 = (idx & 15) * 8;
            uint4 v = *reinterpret_cast<const uint4*>(T + hd * TPAD + ch8);
            *reinterpret_cast<uint4*>(base + (size_t)hd * kS + s0 + ch8) = v;
        }
    } else {
        __half* out = (seg == 0) ? g_Qh : g_Kh;
        const int heads = (seg == 0) ? kNH : kGH;
        #pragma unroll
        for (int half = 0; half < 2; ++half) {
            const int s = s0 + w * 16 + lr + half * 8;
            #pragma unroll
            for (int nf = 0; nf < 8; ++nf) {
                const int c = colLoc + nf * 8 + 2 * lc;
                const int h = c / kHD, cc = c - h * kHD;
                const float v0 = acc[nf][half * 2 + 0] + bias[c];
                const float v1 = acc[nf][half * 2 + 1] + bias[c + 1];
                __half* dst = out + ((size_t)(bb * heads + h) * kS + s) * kHD + cc;
                *reinterpret_cast<uint32_t*>(dst) = pack_f16(v0, v1);
            }
        }
    }
}

__global__ __launch_bounds__(256) void gemm_out(
    const float* __restrict__ bias, float* __restrict__ out)
{
    extern __shared__ char smem[];
    const uint32_t sb = smem_u32(smem);
    const int tid = threadIdx.x;
    const int lane = tid & 31;
    const int w = tid >> 5;
    const int lr = lane >> 2, lc = lane & 3;
    const int rowBase = blockIdx.y * 128;
    const int colBase = blockIdx.x * 64;

    float acc[8][4];
    #pragma unroll
    for (int i = 0; i < 8; ++i)
        #pragma unroll
        for (int j = 0; j < 4; ++j) acc[i][j] = 0.f;

    gemm16_mainloop(sb, smem, g_Oh + (size_t)rowBase * kD,
                    g_WoT + (size_t)colBase * kD, w, lr, lc, tid, acc);

    #pragma unroll
    for (int half = 0; half < 2; ++half) {
        const int r = rowBase + w * 16 + lr + half * 8;
        #pragma unroll
        for (int nf = 0; nf < 8; ++nf) {
            const int c = colBase + nf * 8 + 2 * lc;
            float* dst = out + (size_t)r * kD + c;
            dst[0] = acc[nf][half * 2 + 0] + bias[c];
            dst[1] = acc[nf][half * 2 + 1] + bias[c + 1];
        }
    }
}

// ---------------------------------------------------------------------------
// Attention: 128-key pipeline stages (ntiles = qt+1), masked-tail skip, LPT,
// ones-mma rowsum, diag masking only on tile kt == qt.
// Stage = K[128][72] + V^T[64][136] = 35840 B; 3 stages = 107520 B;
// Q overlaid on stage 2 (dead after register hoist). 2 CTAs/SM.
// ---------------------------------------------------------------------------
namespace {
constexpr int KST2 = 72;                        // K tile row stride (halves)
constexpr int VST2 = 136;                       // V^T tile row stride (halves)
constexpr int TILE_K_B = 128 * KST2 * 2;        // 18432
constexpr int TILE_V_B = 64 * VST2 * 2;         // 17408
constexpr int STAGE_B = TILE_K_B + TILE_V_B;    // 35840
constexpr int SMEM_ATTN = 3 * STAGE_B;          // 107520
constexpr uint32_t ONE2 = 0x3C003C00u;          // f16x2 {1.0, 1.0}
}

__global__ __launch_bounds__(256, 2) void attn_mma()
{
    extern __shared__ char smem[];
    const uint32_t sb = smem_u32(smem);

    const int tid = threadIdx.x;
    const int lane = tid & 31;
    const int w = tid >> 5;
    const int id = blockIdx.x;
    const int qt = 15 - id / 24;                // global LPT
    const int pair = id % 24;
    const int h = pair % kNH, b = pair / kNH;
    const int g = h / kREP;
    const int lr = lane >> 2, lc = lane & 3;
    const int ntiles = qt + 1;                  // 128-key tiles
    const int ktmax64 = 2 * qt + 2;             // for Vsuf / tail

    const __half* Qp = g_Qh + ((size_t)(b * kNH + h) * kS + (size_t)qt * 128) * kHD;
    const __half* Kp = g_Kh + (size_t)(b * kGH + g) * kS * kHD;
    const __half* Vp = g_Vh + (size_t)(b * kGH + g) * kHD * kS;

    auto stage_tile = [&](int kt, int s) {
        const __half* Kt = Kp + (size_t)kt * 128 * kHD;
        const uint32_t kb = sb + s * STAGE_B;
        const uint32_t vb = kb + TILE_K_B;
        #pragma unroll
        for (int j = 0; j < 4; ++j) {
            const int c = tid + 256 * j;        // 0..1023
            const int r = c >> 3, c8 = (c & 7) * 8;
            cp16(kb + (uint32_t)(r * KST2 + c8) * 2, Kt + (size_t)r * kHD + c8);
        }
        #pragma unroll
        for (int j = 0; j < 4; ++j) {
            const int c = tid + 256 * j;        // 0..1023
            const int r = c >> 4, c8 = (c & 15) * 8;   // hd row, key col base
            cp16(vb + (uint32_t)(r * VST2 + c8) * 2,
                 Vp + (size_t)r * kS + (size_t)kt * 128 + c8);
        }
        cp_commit();
    };

    stage_tile(0, 0);
    if (ntiles > 1) stage_tile(1, 1);
    else cp_commit();                            // keep wait_group(1) sound

    // stage Q into stage-2 region (dead after hoist; stage 2 first written
    // by the in-loop prefetch which happens after the hoist)
    __half* Qs = reinterpret_cast<__half*>(smem + 2 * STAGE_B);
    #pragma unroll
    for (int j = 0; j < 4; ++j) {
        const int c = tid + 256 * j;
        const int r = c >> 3, c8 = (c & 7) * 8;
        uint4 v = *reinterpret_cast<const uint4*>(Qp + (size_t)r * kHD + c8);
        *reinterpret_cast<uint4*>(Qs + r * KST2 + c8) = v;
    }
    __syncthreads();

    uint32_t qa[4][4];
    {
        const int r0 = w * 16 + lr;
        #pragma unroll
        for (int ks = 0; ks < 4; ++ks) {
            const int cb = ks * 16 + 2 * lc;
            qa[ks][0] = ld32s(Qs + r0 * KST2 + cb);
            qa[ks][1] = ld32s(Qs + (r0 + 8) * KST2 + cb);
            qa[ks][2] = ld32s(Qs + r0 * KST2 + cb + 8);
            qa[ks][3] = ld32s(Qs + (r0 + 8) * KST2 + cb + 8);
        }
    }
    __syncthreads();    // all warps hoisted before stage-2 region is reused

    float oacc[8][4];
    #pragma unroll
    for (int i = 0; i < 8; ++i)
        #pragma unroll
        for (int j = 0; j < 4; ++j) oacc[i][j] = 0.f;
    float lacc[4] = {0.f, 0.f, 0.f, 0.f};
    const int q0 = qt * 128 + w * 16 + lr;

    int buf = 0;
    for (int kt = 0; kt < ntiles; ++kt) {
        cp_wait1();
        __syncthreads();

        const __half* Kb = reinterpret_cast<const __half*>(smem + buf * STAGE_B);
        const __half* Vb = reinterpret_cast<const __half*>(
            smem + buf * STAGE_B + TILE_K_B);
        const bool diag = (kt == qt);           // only the last tile is masked

        #pragma unroll
        for (int sub = 0; sub < 4; ++sub) {
            float sacc[4][4];
            #pragma unroll
            for (int i = 0; i < 4; ++i)
                #pragma unroll
                for (int j = 0; j < 4; ++j) sacc[i][j] = 0.f;

            #pragma unroll
            for (int nf = 0; nf < 4; ++nf) {
                const __half* krow = Kb + (sub * 32 + nf * 8 + lr) * KST2;
                #pragma unroll
                for (int ks = 0; ks < 4; ++ks) {
                    mma_f16(sacc[nf], qa[ks],
                            ld32s(krow + ks * 16 + 2 * lc),
                            ld32s(krow + ks * 16 + 2 * lc + 8));
                }
            }

            uint32_t pa[2][4];
            if (diag) {
                #pragma unroll
                for (int nf = 0; nf < 4; ++nf) {
                    const int colb = kt * 128 + sub * 32 + nf * 8 + 2 * lc;
                    const float p0 = (colb     <= q0)     ? ex2(sacc[nf][0] * kScaleL2) : 1.0f;
                    const float p1 = (colb + 1 <= q0)     ? ex2(sacc[nf][1] * kScaleL2) : 1.0f;
                    const float p2 = (colb     <= q0 + 8) ? ex2(sacc[nf][2] * kScaleL2) : 1.0f;
                    const float p3 = (colb + 1 <= q0 + 8) ? ex2(sacc[nf][3] * kScaleL2) : 1.0f;
                    const int kk = nf >> 1;
                    if ((nf & 1) == 0) {
                        pa[kk][0] = pack_f16(p0, p1);
                        pa[kk][1] = pack_f16(p2, p3);
                    } else {
                        pa[kk][2] = pack_f16(p0, p1);
                        pa[kk][3] = pack_f16(p2, p3);
                    }
                }
            } else {
                #pragma unroll
                for (int nf = 0; nf < 4; ++nf) {
                    const float p0 = ex2(sacc[nf][0] * kScaleL2);
                    const float p1 = ex2(sacc[nf][1] * kScaleL2);
                    const float p2 = ex2(sacc[nf][2] * kScaleL2);
                    const float p3 = ex2(sacc[nf][3] * kScaleL2);
                    const int kk = nf >> 1;
                    if ((nf & 1) == 0) {
                        pa[kk][0] = pack_f16(p0, p1);
                        pa[kk][1] = pack_f16(p2, p3);
                    } else {
                        pa[kk][2] = pack_f16(p0, p1);
                        pa[kk][3] = pack_f16(p2, p3);
                    }
                }
            }

            // PV + rowsum (B = ones)
            #pragma unroll
            for (int kk = 0; kk < 2; ++kk)
                mma_f16(lacc, pa[kk], ONE2, ONE2);
            #pragma unroll
            for (int nd = 0; nd < 8; ++nd) {
                const __half* vrow = Vb + (nd * 8 + lr) * VST2 + sub * 32;
                #pragma unroll
                for (int kk = 0; kk < 2; ++kk) {
                    mma_f16(oacc[nd], pa[kk],
                            ld32s(vrow + kk * 16 + 2 * lc),
                            ld32s(vrow + kk * 16 + 2 * lc + 8));
                }
            }
        }

        if (kt + 2 < ntiles) stage_tile(kt + 2, (buf + 2) % 3);
        else cp_commit();
        buf = (buf + 1) % 3;
    }

    // fully-masked suffix: O += colsum(V[ktmax64*64:]); lsum += tail count
    const float* suf = g_Vsuf + ((size_t)(b * kGH + g) * 33 + ktmax64) * kHD;
    #pragma unroll
    for (int nd = 0; nd < 8; ++nd) {
        const int hd = nd * 8 + 2 * lc;
        const float s0v = suf[hd], s1v = suf[hd + 1];
        oacc[nd][0] += s0v; oacc[nd][1] += s1v;
        oacc[nd][2] += s0v; oacc[nd][3] += s1v;
    }

    const float tail = (float)(kS - ktmax64 * 64);
    const float inv0 = 1.f / (lacc[0] + tail);
    const float inv1 = 1.f / (lacc[2] + tail);

    __half* Op = g_Oh + (size_t)(b * kNH + h) * kHD * kS;
    #pragma unroll
    for (int nd = 0; nd < 8; ++nd) {
        const int hd = nd * 8 + 2 * lc;
        Op[(size_t)hd * kS + q0]           = __float2half_rn(oacc[nd][0] * inv0);
        Op[(size_t)(hd + 1) * kS + q0]     = __float2half_rn(oacc[nd][1] * inv0);
        Op[(size_t)hd * kS + q0 + 8]       = __float2half_rn(oacc[nd][2] * inv1);
        Op[(size_t)(hd + 1) * kS + q0 + 8] = __float2half_rn(oacc[nd][3] * inv1);
    }
}

extern "C" void kernel_launch(void* const* d_in, const int* in_sizes, int n_in,
                              void* d_out, int out_size)
{
    (void)in_sizes; (void)n_in; (void)out_size;
    const float* x  = (const float*)d_in[0];
    const float* Wq = (const float*)d_in[2];
    const float* bq = (const float*)d_in[3];
    const float* Wk = (const float*)d_in[4];
    const float* bk = (const float*)d_in[5];
    const float* Wv = (const float*)d_in[6];
    const float* bv = (const float*)d_in[7];
    const float* Wo = (const float*)d_in[8];
    const float* bo = (const float*)d_in[9];
    float* out = (float*)d_out;

    cudaFuncSetAttribute(attn_mma, cudaFuncAttributeMaxDynamicSharedMemorySize, SMEM_ATTN);
    cudaFuncSetAttribute(gemm_qkv, cudaFuncAttributeMaxDynamicSharedMemorySize, SMEM_GEMM);
    cudaFuncSetAttribute(gemm_out, cudaFuncAttributeMaxDynamicSharedMemorySize, SMEM_GEMM);

    convert_all<<<3072 + 1536, 256>>>(x, Wq, Wk, Wv, Wo);

    gemm_qkv<<<dim3(1280 / 64, (kB * kS) / 128), 256, SMEM_GEMM>>>(bq, bk, bv);

    vsuf_kernel<<<64, 256>>>();

    attn_mma<<<kS / 128 * kNH * kB, 256, SMEM_ATTN>>>();

    gemm_out<<<dim3(kD / 64, (kB * kS) / 128), 256, SMEM_GEMM>>>(bo, out);
}